// round 1
// baseline (speedup 1.0000x reference)
#include <cuda_runtime.h>
#include <cuda_bf16.h>

// Problem constants
#define BATCH 1024
#define HID   512
#define TSZ   24
#define PLEN  256

// Layer-kernel tiling
#define BM 128      // batch rows per CTA
#define BN 32       // gate columns per CTA (each has 3 weight parts r/z/n)
#define BK 8        // k-slice
#define APAD 4

// Output-head tiling
#define OBM 64
#define OBK 32

// Ping-pong state buffers (device globals: no allocation allowed)
__device__ float g_h0[2][BATCH * HID];
__device__ float g_h1[2][BATCH * HID];
__device__ float g_val[2][BATCH * TSZ];

// ---------------------------------------------------------------------------
// helpers
// ---------------------------------------------------------------------------
union F2U { float2 f; unsigned long long u; };

__device__ __forceinline__ void ffma2(float2& d, const float2 a, const float2 b) {
    F2U D, A, B;
    D.f = d; A.f = a; B.f = b;
    asm("fma.rn.f32x2 %0, %1, %2, %0;" : "+l"(D.u) : "l"(A.u), "l"(B.u));
    d = D.f;
}

__device__ __forceinline__ float sigf(float x) {
    return 1.0f / (1.0f + __expf(-x));
}
__device__ __forceinline__ float tanhf_fast(float x) {
    return 1.0f - 2.0f / (__expf(2.0f * x) + 1.0f);
}

// ---------------------------------------------------------------------------
// Fused GRU layer: h' = GRUCell(x, h)
//   G*[b,j] accumulated over K = KX (input phase, Wih) then HID (hidden, Whh)
//   4 accumulators per (b,j): r-sum, z-sum, n-input, n-hidden
// Grid: (BATCH/BM, HID/BN), block 256
// ---------------------------------------------------------------------------
template<int KX>
__global__ __launch_bounds__(256, 2)
void gru_layer_kernel(const float* __restrict__ x,
                      const float* __restrict__ hin,
                      float* __restrict__ hout,
                      const float* __restrict__ Wih,
                      const float* __restrict__ Whh,
                      const float* __restrict__ bih,
                      const float* __restrict__ bhh)
{
    __shared__ __align__(16) float  As[BK][BM + APAD];
    __shared__ __align__(16) float2 Ws[BK][3][BN];   // weights pre-duplicated (w,w)

    const int tid = threadIdx.x;
    const int tm  = tid & 15;    // row group: handles row-pairs tm*2 + 32*p
    const int tn  = tid >> 4;    // 0..15 -> cols tn*2, tn*2+1
    const int jj  = tn * 2;
    const int rowBase = blockIdx.x * BM;
    const int colBase = blockIdx.y * BN;

    // accumulators: [pair p][col c], .x = row0 of pair, .y = row1
    float2 aR[4][2], aZ[4][2], aN[4][2], aH[4][2];

    // init with biases
    #pragma unroll
    for (int c = 0; c < 2; c++) {
        const int j = colBase + jj + c;
        const float br = bih[j]           + bhh[j];
        const float bz = bih[HID + j]     + bhh[HID + j];
        const float bi = bih[2 * HID + j];
        const float bh = bhh[2 * HID + j];
        #pragma unroll
        for (int p = 0; p < 4; p++) {
            aR[p][c] = make_float2(br, br);
            aZ[p][c] = make_float2(bz, bz);
            aN[p][c] = make_float2(bi, bi);
            aH[p][c] = make_float2(bh, bh);
        }
    }

    // loader mapping
    const int  lb = tid >> 1;            // 0..127 (row)
    const int  lk = (tid & 1) << 2;      // 0 or 4
    const bool wl = tid < 192;
    const int  wg = tid / 64;            // gate 0..2
    const int  wj = (tid & 63) >> 1;     // 0..31 (local col)
    const int  wk = (tid & 1) << 2;      // 0 or 4

    #pragma unroll
    for (int ph = 0; ph < 2; ph++) {
        const float* __restrict__ A = ph ? hin : x;
        const float* __restrict__ W = ph ? Whh : Wih;
        const int K = ph ? HID : KX;
        float2 (*aNt)[2] = ph ? aH : aN;   // n-part target

        const float* Arow = A + (size_t)(rowBase + lb) * K + lk;
        const float* Wrow = wl ? (W + (size_t)(wg * HID + colBase + wj) * K + wk) : W;

        float4 av = *(const float4*)(Arow);
        float4 wv = wl ? *(const float4*)(Wrow) : make_float4(0.f, 0.f, 0.f, 0.f);

        for (int k0 = 0; k0 < K; k0 += BK) {
            // stage current tile
            #pragma unroll
            for (int i = 0; i < 4; i++)
                As[lk + i][lb] = ((const float*)&av)[i];
            if (wl) {
                #pragma unroll
                for (int i = 0; i < 4; i++) {
                    const float w = ((const float*)&wv)[i];
                    Ws[wk + i][wg][wj] = make_float2(w, w);
                }
            }
            __syncthreads();

            // prefetch next tile into registers
            const bool more = (k0 + BK) < K;
            if (more) {
                av = *(const float4*)(Arow + k0 + BK);
                if (wl) wv = *(const float4*)(Wrow + k0 + BK);
            }

            // compute
            #pragma unroll
            for (int kk = 0; kk < BK; kk++) {
                float2 a[4];
                #pragma unroll
                for (int p = 0; p < 4; p++)
                    a[p] = *(const float2*)&As[kk][tm * 2 + 32 * p];
                #pragma unroll
                for (int c = 0; c < 2; c++) {
                    const float2 wr = Ws[kk][0][jj + c];
                    const float2 wz = Ws[kk][1][jj + c];
                    const float2 wn = Ws[kk][2][jj + c];
                    #pragma unroll
                    for (int p = 0; p < 4; p++) {
                        ffma2(aR[p][c],  a[p], wr);
                        ffma2(aZ[p][c],  a[p], wz);
                        ffma2(aNt[p][c], a[p], wn);
                    }
                }
            }
            __syncthreads();
        }
    }

    // GRU epilogue: r=sig, z=sig, n=tanh(in + r*hn), h' = (1-z)*n + z*h
    #pragma unroll
    for (int p = 0; p < 4; p++) {
        const int r0 = rowBase + tm * 2 + 32 * p;
        const float2 hp0 = *(const float2*)&hin[(size_t)r0 * HID + colBase + jj];
        const float2 hp1 = *(const float2*)&hin[(size_t)(r0 + 1) * HID + colBase + jj];
        float o0[2], o1[2];
        #pragma unroll
        for (int c = 0; c < 2; c++) {
            const float rr0 = sigf(aR[p][c].x);
            const float rr1 = sigf(aR[p][c].y);
            const float zz0 = sigf(aZ[p][c].x);
            const float zz1 = sigf(aZ[p][c].y);
            const float nn0 = tanhf_fast(aN[p][c].x + rr0 * aH[p][c].x);
            const float nn1 = tanhf_fast(aN[p][c].y + rr1 * aH[p][c].y);
            const float h0c = (c == 0) ? hp0.x : hp0.y;
            const float h1c = (c == 0) ? hp1.x : hp1.y;
            o0[c] = (1.0f - zz0) * nn0 + zz0 * h0c;
            o1[c] = (1.0f - zz1) * nn1 + zz1 * h1c;
        }
        *(float2*)&hout[(size_t)r0 * HID + colBase + jj]       = make_float2(o0[0], o0[1]);
        *(float2*)&hout[(size_t)(r0 + 1) * HID + colBase + jj] = make_float2(o1[0], o1[1]);
    }
}

// ---------------------------------------------------------------------------
// Output head: out = sigmoid(relu(h1) @ Wout^T + bout)  (B x 24)
// Also feeds next step's val. Grid: BATCH/OBM, block 256.
// ---------------------------------------------------------------------------
__global__ __launch_bounds__(256)
void out_kernel(const float* __restrict__ h1,
                const float* __restrict__ Wout,
                const float* __restrict__ bout,
                float* __restrict__ outputs,
                float* __restrict__ val_out,
                int step)
{
    __shared__ __align__(16) float As[OBK][OBM + 2];
    __shared__ __align__(16) float Bs[OBK][TSZ];

    const int tid = threadIdx.x;
    const int tm = tid & 31;          // row pair: rows tm*2, tm*2+1
    const int tn = tid >> 5;          // 0..7 -> cols tn*3 .. tn*3+2
    const int rowBase = blockIdx.x * OBM;

    float2 acc[3];
    #pragma unroll
    for (int c = 0; c < 3; c++) acc[c] = make_float2(0.f, 0.f);

    // loaders: A 64x32 = 2048 floats -> 2 float4 per thread
    const int  lb = tid >> 2;         // 0..63
    const int  lk = (tid & 3) << 2;   // 0,4,8,12 (and +16)
    const bool wload = tid < 192;
    const int  wj = tid >> 3;         // 0..23
    const int  wk = (tid & 7) << 2;   // 0..28

    const float* Arow = h1 + (size_t)(rowBase + lb) * HID + lk;
    const float* Wrow = wload ? (Wout + (size_t)wj * HID + wk) : Wout;

    float4 av0 = *(const float4*)(Arow);
    float4 av1 = *(const float4*)(Arow + 16);
    float4 wv  = wload ? *(const float4*)(Wrow) : make_float4(0.f, 0.f, 0.f, 0.f);

    for (int k0 = 0; k0 < HID; k0 += OBK) {
        #pragma unroll
        for (int i = 0; i < 4; i++) {
            As[lk + i][lb]      = fmaxf(((const float*)&av0)[i], 0.f);
            As[lk + 16 + i][lb] = fmaxf(((const float*)&av1)[i], 0.f);
        }
        if (wload) {
            #pragma unroll
            for (int i = 0; i < 4; i++)
                Bs[wk + i][wj] = ((const float*)&wv)[i];
        }
        __syncthreads();

        const bool more = (k0 + OBK) < HID;
        if (more) {
            av0 = *(const float4*)(Arow + k0 + OBK);
            av1 = *(const float4*)(Arow + k0 + OBK + 16);
            if (wload) wv = *(const float4*)(Wrow + k0 + OBK);
        }

        #pragma unroll
        for (int kk = 0; kk < OBK; kk++) {
            const float2 a = *(const float2*)&As[kk][tm * 2];
            #pragma unroll
            for (int c = 0; c < 3; c++) {
                const float w = Bs[kk][tn * 3 + c];
                acc[c].x = fmaf(a.x, w, acc[c].x);
                acc[c].y = fmaf(a.y, w, acc[c].y);
            }
        }
        __syncthreads();
    }

    const int r0 = rowBase + tm * 2;
    #pragma unroll
    for (int c = 0; c < 3; c++) {
        const int j = tn * 3 + c;
        const float bb = bout[j];
        const float v0 = sigf(acc[c].x + bb);
        const float v1 = sigf(acc[c].y + bb);
        outputs[(size_t)r0 * (PLEN * TSZ) + (size_t)step * TSZ + j]       = v0;
        outputs[(size_t)(r0 + 1) * (PLEN * TSZ) + (size_t)step * TSZ + j] = v1;
        val_out[r0 * TSZ + j]       = v0;
        val_out[(r0 + 1) * TSZ + j] = v1;
    }
}

// ---------------------------------------------------------------------------
// init / final copy
// ---------------------------------------------------------------------------
__global__ void init_kernel(const float* __restrict__ hidden,
                            float* __restrict__ h0,
                            float* __restrict__ h1,
                            float* __restrict__ val)
{
    const int i = blockIdx.x * blockDim.x + threadIdx.x;
    if (i < BATCH * HID) {
        h0[i] = hidden[i];
        h1[i] = hidden[BATCH * HID + i];
    }
    if (i < BATCH * TSZ) val[i] = 0.0f;
}

__global__ void fin_kernel(const float* __restrict__ h0,
                           const float* __restrict__ h1,
                           float* __restrict__ dst)
{
    const int i = blockIdx.x * blockDim.x + threadIdx.x;
    if (i < BATCH * HID) {
        dst[i] = h0[i];
        dst[BATCH * HID + i] = h1[i];
    }
}

// ---------------------------------------------------------------------------
// host: record the full 256-step rollout into the capture stream
// ---------------------------------------------------------------------------
extern "C" void kernel_launch(void* const* d_in, const int* in_sizes, int n_in,
                              void* d_out, int out_size)
{
    const float* hidden = (const float*)d_in[0];
    const float* Wih0   = (const float*)d_in[1];
    const float* Whh0   = (const float*)d_in[2];
    const float* bih0   = (const float*)d_in[3];
    const float* bhh0   = (const float*)d_in[4];
    const float* Wih1   = (const float*)d_in[5];
    const float* Whh1   = (const float*)d_in[6];
    const float* bih1   = (const float*)d_in[7];
    const float* bhh1   = (const float*)d_in[8];
    const float* Wout   = (const float*)d_in[9];
    const float* bout   = (const float*)d_in[10];
    float* out = (float*)d_out;

    float *h0b, *h1b, *vb;
    cudaGetSymbolAddress((void**)&h0b, g_h0);
    cudaGetSymbolAddress((void**)&h1b, g_h1);
    cudaGetSymbolAddress((void**)&vb,  g_val);
    float* h0p[2]  = { h0b, h0b + BATCH * HID };
    float* h1p[2]  = { h1b, h1b + BATCH * HID };
    float* valp[2] = { vb,  vb  + BATCH * TSZ };

    init_kernel<<<(BATCH * HID + 255) / 256, 256>>>(hidden, h0p[0], h1p[0], valp[0]);

    const dim3 lgrid(BATCH / BM, HID / BN);
    for (int s = 0; s < PLEN; s++) {
        const int cur = s & 1;
        const int nxt = cur ^ 1;
        gru_layer_kernel<TSZ><<<lgrid, 256>>>(valp[cur], h0p[cur], h0p[nxt],
                                              Wih0, Whh0, bih0, bhh0);
        gru_layer_kernel<HID><<<lgrid, 256>>>(h0p[nxt], h1p[cur], h1p[nxt],
                                              Wih1, Whh1, bih1, bhh1);
        out_kernel<<<BATCH / OBM, 256>>>(h1p[nxt], Wout, bout, out, valp[nxt], s);
    }
    // after 256 steps (even), final hidden sits in buffer index 0
    fin_kernel<<<(BATCH * HID + 255) / 256, 256>>>(h0p[0], h1p[0],
                                                   out + (size_t)BATCH * PLEN * TSZ);
}